// round 2
// baseline (speedup 1.0000x reference)
#include <cuda_runtime.h>
#include <math.h>

#define E_TOTAL   480000
#define NN        30000
#define NG        512
#define TBL       8192
#define RMAX      3.5f
#define INV_NN    0.2631578947368421f    // 1/3.8
#define INV_SQNN  0.5129891760425771f    // 1/sqrt(3.8)

// ---------------- scratch (__device__ globals; no allocation allowed) -------
__device__ float g_sh [E_TOTAL*16];
__device__ float g_r  [E_TOTAL];
__device__ float g_x0 [NN*16];
__device__ float g_x1 [NN*160];
__device__ float g_xg [NN*128];
__device__ float g_B1 [256*160];   // cg1 transposed, * 1/3.8
__device__ float g_B2 [128*112];   // cg2 transposed, * 1/(2*sqrt(3.8))
__device__ float g_tw1[TBL*160];
__device__ float g_tw2[TBL*8];

// ---------------- zero ------------------------------------------------------
__global__ void zero_kernel(float* out){
    int i = blockIdx.x*blockDim.x + threadIdx.x;
    int s = gridDim.x*blockDim.x;
    for (int k=i; k<NN*16;  k+=s) g_x0[k]=0.f;
    for (int k=i; k<NN*160; k+=s) g_x1[k]=0.f;
    for (int k=i; k<NG*7;   k+=s) out[k]=0.f;
}

// ---------------- B matrices (transpose + fold scales) ----------------------
__global__ void buildB_kernel(const float* __restrict__ cg1,
                              const float* __restrict__ cg2){
    int i = blockIdx.x*blockDim.x + threadIdx.x;
    int s = gridDim.x*blockDim.x;
    for (int idx=i; idx<256*160; idx+=s){
        int K = idx/160, k = idx%160;
        g_B1[idx] = cg1[k*256 + K] * INV_NN;
    }
    for (int idx=i; idx<128*112; idx+=s){
        int I = idx/112, c = idx%112;
        int k = c >> 4, j = c & 15;
        g_B2[idx] = cg2[k*2048 + I*16 + j] * (0.5f * INV_SQNN);
    }
}

// ---------------- radial embed ---------------------------------------------
__device__ __forceinline__ void radial3(float r, float* emb){
    const float C = 1.14136f * 7.389056098930650f;   // 1.14136*e^2
    #pragma unroll
    for (int i=0;i<3;i++){
        float u = r - (0.5f + (float)i);
        float d = u*u - 1.0f;
        emb[i] = (d < 0.f) ? C * expf(1.0f/d) * 1.7320508075688772f : 0.f;
    }
}

// ---------------- MLP lookup tables (16 entries / block) --------------------
__global__ void build_table(const float* __restrict__ W1a, const float* __restrict__ W2a,
                            const float* __restrict__ W1b, const float* __restrict__ W2b){
    __shared__ float hs [16][256];
    __shared__ float h2s[16][256];
    int base = blockIdx.x*16;
    const float s1 = 0.5773502691896258f; // 1/sqrt(3)
    for (int idx=threadIdx.x; idx<16*256; idx+=256){
        int el = idx>>8, c = idx&255;
        float r = (float)(base+el) * (RMAX/(float)(TBL-1));
        float emb[3]; radial3(r, emb);
        float a = (emb[0]*W1a[c] + emb[1]*W1a[256+c] + emb[2]*W1a[512+c]) * s1;
        hs [el][c] = fmaxf(a, 0.f);
        float b = (emb[0]*W1b[c] + emb[1]*W1b[256+c] + emb[2]*W1b[512+c]) * s1;
        h2s[el][c] = fmaxf(b, 0.f);
    }
    __syncthreads();
    for (int idx=threadIdx.x; idx<16*160; idx+=256){
        int el = idx/160, k = idx%160;
        float acc = 0.f;
        #pragma unroll 4
        for (int c=0;c<256;c++) acc += hs[el][c]*W2a[c*160+k];
        g_tw1[(base+el)*160+k] = acc * 0.0625f;
    }
    for (int idx=threadIdx.x; idx<16*7; idx+=256){
        int el = idx/7, k = idx%7;
        float acc = 0.f;
        #pragma unroll 4
        for (int c=0;c<256;c++) acc += h2s[el][c]*W2b[c*7+k];
        g_tw2[(base+el)*8+k] = acc * 0.0625f;
    }
}

// ---------------- per-edge geometry: sh, r, segsum(sh) ----------------------
__global__ void edge_geom(const float* __restrict__ pos,
                          const int* __restrict__ esrc,
                          const int* __restrict__ edst){
    int e = blockIdx.x*blockDim.x + threadIdx.x;
    if (e >= E_TOTAL) return;
    int s = esrc[e], d = edst[e];
    float ex = pos[s*3+0]-pos[d*3+0];
    float ey = pos[s*3+1]-pos[d*3+1];
    float ez = pos[s*3+2]-pos[d*3+2];
    float r  = sqrtf(ex*ex+ey*ey+ez*ez);
    g_r[e] = r;
    float inv = 1.0f/fmaxf(r, 1e-9f);
    float x = ex*inv, y = ey*inv, z = ez*inv;
    float x2=x*x, y2=y*y, z2=z*z;
    const float s3   = 1.7320508075688772f;  // sqrt3
    const float s15  = 3.8729833462074170f;  // sqrt15
    const float s15h = 1.9364916731037085f;  // sqrt15/2
    const float s5h  = 1.1180339887498949f;  // sqrt5/2
    const float s358 = 2.0916500663351889f;  // sqrt(35/8)
    const float s105 = 10.246950765959598f;  // sqrt105
    const float s218 = 1.6201851746019651f;  // sqrt(21/8)
    const float s7h  = 1.3228756555322954f;  // sqrt7/2
    const float s105h= 5.1234753829797990f;  // sqrt105/2
    float sh[16];
    sh[0]=1.f;
    sh[1]=s3*x;  sh[2]=s3*y;  sh[3]=s3*z;
    sh[4]=s15*x*y; sh[5]=s15*y*z; sh[6]=s5h*(3.f*z2-1.f); sh[7]=s15*x*z; sh[8]=s15h*(x2-y2);
    sh[9]=s358*y*(3.f*x2-y2); sh[10]=s105*x*y*z; sh[11]=s218*y*(5.f*z2-1.f);
    sh[12]=s7h*z*(5.f*z2-3.f); sh[13]=s218*x*(5.f*z2-1.f); sh[14]=s105h*z*(x2-y2);
    sh[15]=s358*x*(x2-y2);
    float4* o = (float4*)(g_sh + (size_t)e*16);
    o[0] = make_float4(sh[0], sh[1], sh[2], sh[3]);
    o[1] = make_float4(sh[4], sh[5], sh[6], sh[7]);
    o[2] = make_float4(sh[8], sh[9], sh[10],sh[11]);
    o[3] = make_float4(sh[12],sh[13],sh[14],sh[15]);
    float* xp = g_x0 + (size_t)d*16;
    #pragma unroll
    for (int j=0;j<16;j++) atomicAdd(xp+j, sh[j]);
}

// ---------------- conv1: EF = (xs outer sh) @ B1, *w1(r), scatter ----------
// block: 256 thr = 8 warps; 64 edges/block; warp w owns edges [8w,8w+8);
// lane l accumulates k in {l, l+32, ..., l+128}. K processed in 2 chunks of 128.
__global__ __launch_bounds__(256) void conv1_kernel(const int* __restrict__ esrc,
                                                    const int* __restrict__ edst){
    __shared__ float As  [64*128];
    __shared__ float xs_s[64*16];
    __shared__ float sh_s[64*16];
    __shared__ int   src_s[64];
    int e0 = blockIdx.x*64;
    if (threadIdx.x < 64) src_s[threadIdx.x] = esrc[e0+threadIdx.x];
    __syncthreads();
    for (int idx=threadIdx.x; idx<64*16; idx+=256){
        int el = idx>>4, c = idx&15;
        xs_s[idx] = g_x0[(size_t)src_s[el]*16 + c];
        sh_s[idx] = g_sh[((size_t)(e0+el))*16 + c];
    }
    int lane = threadIdx.x & 31;
    int wid  = threadIdx.x >> 5;
    float acc[8][5];
    #pragma unroll
    for (int e=0;e<8;e++)
        #pragma unroll
        for (int t=0;t<5;t++) acc[e][t]=0.f;

    for (int kc=0; kc<2; kc++){
        __syncthreads();
        for (int idx=threadIdx.x; idx<64*128; idx+=256){
            int el = idx>>7, Kl = idx&127;
            int K = kc*128 + Kl;
            As[idx] = xs_s[(el<<4)+(K>>4)] * sh_s[(el<<4)+(K&15)];
        }
        __syncthreads();
        const float* Ab = As + (wid*8)*128;
        const float* Bb = g_B1 + (kc*128)*160 + lane;
        #pragma unroll 2
        for (int Kl=0; Kl<128; Kl++){
            float b0 = Bb[Kl*160 +   0];
            float b1 = Bb[Kl*160 +  32];
            float b2 = Bb[Kl*160 +  64];
            float b3 = Bb[Kl*160 +  96];
            float b4 = Bb[Kl*160 + 128];
            #pragma unroll
            for (int e=0;e<8;e++){
                float a = Ab[e*128 + Kl];
                acc[e][0] += a*b0; acc[e][1] += a*b1; acc[e][2] += a*b2;
                acc[e][3] += a*b3; acc[e][4] += a*b4;
            }
        }
    }
    // epilogue: *w1 (table lerp), scatter-add to x1[dst]
    #pragma unroll
    for (int e=0;e<8;e++){
        int ge = e0 + wid*8 + e;
        float r = g_r[ge];
        if (r >= RMAX) continue;          // w1 == 0 exactly
        float tc = r * ((float)(TBL-1)/RMAX);
        int   i0 = (int)tc; if (i0 > TBL-2) i0 = TBL-2;
        float f  = tc - (float)i0;
        int   d  = edst[ge];
        const float* t0 = g_tw1 + (size_t)i0*160 + lane;
        float* xp = g_x1 + (size_t)d*160 + lane;
        #pragma unroll
        for (int t=0;t<5;t++){
            float lo = t0[t*32], hi = t0[t*32+160];
            float w = lo + f*(hi-lo);
            atomicAdd(xp + t*32, acc[e][t]*w);
        }
    }
}

// ---------------- gate ------------------------------------------------------
__global__ void gate_kernel(){
    int i = blockIdx.x*blockDim.x + threadIdx.x;
    if (i >= NN*128) return;
    int n = i >> 7, c = i & 127;
    const float* x = g_x1 + (size_t)n*160;
    float o;
    if (c < 16)      o = fmaxf(x[c], 0.f);
    else if (c < 32) o = fabsf(x[c]);
    else {
        int ii = c - 32;          // 0..95
        int v  = ii/3;            // 0..31
        float gv = x[32 + v];
        bool use_relu = (v < 8) || (v >= 16 && v < 24);
        gv = use_relu ? fmaxf(gv, 0.f) : tanhf(gv);
        o = gv * x[64 + ii];
    }
    g_xg[i] = o;
}

// ---------------- conv2: C2 = xg[src] @ B2, contract sh, *w2, scatter ------
// block: 256 thr; 64 edges; group g = tid>>4 owns edges [4g,4g+4); jl = tid&15
// is the j (sh) index; each thread accumulates all 7 k at its j.
__global__ __launch_bounds__(256) void conv2_kernel(const int* __restrict__ esrc,
                                                    const int* __restrict__ edst,
                                                    const int* __restrict__ batch,
                                                    float* __restrict__ out){
    __shared__ float A2s [64*128];
    __shared__ float sh_s[64*16];
    __shared__ int   src_s[64];
    __shared__ int   bdst_s[64];
    int e0 = blockIdx.x*64;
    if (threadIdx.x < 64){
        src_s [threadIdx.x] = esrc[e0+threadIdx.x];
        bdst_s[threadIdx.x] = batch[edst[e0+threadIdx.x]];
    }
    __syncthreads();
    for (int idx=threadIdx.x; idx<64*128; idx+=256){
        int el = idx>>7, c = idx&127;
        A2s[idx] = g_xg[(size_t)src_s[el]*128 + c];
    }
    for (int idx=threadIdx.x; idx<64*16; idx+=256)
        sh_s[idx] = g_sh[(size_t)e0*16 + idx];
    __syncthreads();

    int jl  = threadIdx.x & 15;
    int grp = threadIdx.x >> 4;
    float acc[4][7];
    #pragma unroll
    for (int e=0;e<4;e++)
        #pragma unroll
        for (int t=0;t<7;t++) acc[e][t]=0.f;

    const float* Ab = A2s + grp*4*128;
    const float* Bb = g_B2 + jl;
    #pragma unroll 2
    for (int K=0; K<128; K++){
        float b[7];
        #pragma unroll
        for (int t=0;t<7;t++) b[t] = Bb[K*112 + t*16];
        #pragma unroll
        for (int e=0;e<4;e++){
            float a = Ab[e*128 + K];
            #pragma unroll
            for (int t=0;t<7;t++) acc[e][t] += a*b[t];
        }
    }
    // epilogue: multiply by sh_j, reduce over the 16 j-lanes, *w2, scatter
    #pragma unroll
    for (int e=0;e<4;e++){
        int le = grp*4 + e;
        float shv = sh_s[le*16 + jl];
        float p[7];
        #pragma unroll
        for (int t=0;t<7;t++) p[t] = acc[e][t]*shv;
        #pragma unroll
        for (int off=8; off>=1; off>>=1){
            #pragma unroll
            for (int t=0;t<7;t++)
                p[t] += __shfl_down_sync(0xffffffffu, p[t], off, 16);
        }
        if (jl == 0){
            int ge = e0 + le;
            float r = g_r[ge];
            if (r < RMAX){
                float tc = r * ((float)(TBL-1)/RMAX);
                int   i0 = (int)tc; if (i0 > TBL-2) i0 = TBL-2;
                float f  = tc - (float)i0;
                const float* t0 = g_tw2 + (size_t)i0*8;
                int bg = bdst_s[le];
                #pragma unroll
                for (int k=0;k<7;k++){
                    float lo = t0[k], hi = t0[k+8];
                    float w  = lo + f*(hi-lo);
                    atomicAdd(out + bg*7 + k, p[k]*w);
                }
            }
        }
    }
}

// ---------------- launch ----------------------------------------------------
extern "C" void kernel_launch(void* const* d_in, const int* in_sizes, int n_in,
                              void* d_out, int out_size){
    const float* pos  = (const float*)d_in[0];
    const float* W1a  = (const float*)d_in[1];
    const float* W2a  = (const float*)d_in[2];
    const float* cg1  = (const float*)d_in[3];
    const float* W1b  = (const float*)d_in[4];
    const float* W2b  = (const float*)d_in[5];
    const float* cg2  = (const float*)d_in[6];
    const int*   esrc = (const int*)d_in[7];
    const int*   edst = (const int*)d_in[8];
    const int*   batch= (const int*)d_in[9];
    float* out = (float*)d_out;

    zero_kernel  <<<2048, 256>>>(out);
    buildB_kernel<<<216, 256>>>(cg1, cg2);
    build_table  <<<TBL/16, 256>>>(W1a, W2a, W1b, W2b);
    edge_geom    <<<E_TOTAL/256, 256>>>(pos, esrc, edst);
    conv1_kernel <<<E_TOTAL/64, 256>>>(esrc, edst);
    gate_kernel  <<<(NN*128)/256, 256>>>();
    conv2_kernel <<<E_TOTAL/64, 256>>>(esrc, edst, batch, out);
}